// round 6
// baseline (speedup 1.0000x reference)
#include <cuda_runtime.h>
#include <cuda_bf16.h>
#include <cstdint>
#include <math.h>

// Problem constants
#define NTOK 8192      // B*S
#define DIM  1024
#define NE   8
#define EPSV 1e-4f
#define WTHR 0.1f
#define QMAX 32512.0f  // 15-bit-ish fixed point ceiling (keeps a1 in [-127,127])

// GEMM tile
#define BM 128
#define BN 128
#define BK 64          // k bytes (int8) per chunk
#define NKCH (DIM / BK)   // 16

// smem (dynamic, bytes)
#define ASTRIDE 80                 // 64B row + 16B pad (conflict-free ldmatrix)
#define PLANE   (128 * ASTRIDE)    // 10240 (A: 128 tok rows; B: 128 f rows)
#define OFF_A1  0
#define OFF_A0  PLANE
#define OFF_B1  (2 * PLANE)
#define OFF_B0  (3 * PLANE)
#define STAGE_SZ (4 * PLANE)       // 40960
#define SM_TOK   0
#define SM_WT    512
#define SM_SX    1024
#define SM_SW    1536
#define SM_BIAS  2048
#define SM_TILES 2560
#define SM_TOTAL (SM_TILES + 2 * STAGE_SZ)   // 84480

// -------- device scratch --------
__device__ int   g_cnt[NE];
__device__ int   g_tok[NE][NTOK];     // (token<<1) | slot
__device__ float g_wt [NE][NTOK];
__device__ float g_sx [NTOK];
__device__ int   g_swmax_i[NE * DIM];
__device__ float g_sw [NE * DIM];
__device__ signed char g_xq1[(size_t)NTOK * DIM];
__device__ signed char g_xq0[(size_t)NTOK * DIM];
__device__ signed char g_wq1[(size_t)NE * DIM * DIM];   // [e][f][d] k-major
__device__ signed char g_wq0[(size_t)NE * DIM * DIM];
__device__ float g_part[2ull * NTOK * DIM];

// -------- helpers --------
__device__ __forceinline__ uint32_t smem_u32(const void* p) {
    uint32_t a;
    asm("{ .reg .u64 t; cvta.to.shared.u64 t, %1; cvt.u32.u64 %0, t; }" : "=r"(a) : "l"(p));
    return a;
}
__device__ __forceinline__ void ldsm_x4(uint32_t* r, uint32_t addr) {
    asm volatile("ldmatrix.sync.aligned.m8n8.x4.shared.b16 {%0,%1,%2,%3}, [%4];"
                 : "=r"(r[0]), "=r"(r[1]), "=r"(r[2]), "=r"(r[3]) : "r"(addr));
}
__device__ __forceinline__ void mma_s8(int* d, const uint32_t* a, uint32_t b0, uint32_t b1) {
    asm volatile(
        "mma.sync.aligned.m16n8k32.row.col.s32.s8.s8.s32 "
        "{%0,%1,%2,%3}, {%4,%5,%6,%7}, {%8,%9}, {%0,%1,%2,%3};"
        : "+r"(d[0]), "+r"(d[1]), "+r"(d[2]), "+r"(d[3])
        : "r"(a[0]), "r"(a[1]), "r"(a[2]), "r"(a[3]), "r"(b0), "r"(b1));
}
#define CPA16(dst, src) \
    asm volatile("cp.async.cg.shared.global [%0], [%1], 16;" :: "r"(dst), "l"(src) : "memory")
#define CPA_COMMIT() asm volatile("cp.async.commit_group;" ::: "memory")
#define CPA_WAIT0()  asm volatile("cp.async.wait_group 0;" ::: "memory")

// split a fixed-point int (|X|<=32640) into a1*256 + a0, a1,a0 in s8 range
__device__ __forceinline__ void split_fx(int X, int& a1, int& a0) {
    a1 = (X + 128) >> 8;       // round-to-nearest
    a0 = X - (a1 << 8);        // in [-128, 127]
}

// ================= kernels =================

__global__ void init_kernel() {   // grid 8 x 1024
    g_swmax_i[blockIdx.x * DIM + threadIdx.x] = 0;
    if (blockIdx.x == 0 && threadIdx.x < NE) g_cnt[threadIdx.x] = 0;
}

// gating: one warp per token
__global__ __launch_bounds__(256) void gating_kernel(
    const float* __restrict__ x, const float* __restrict__ gW, const float* __restrict__ gb)
{
    const int warp = threadIdx.x >> 5;
    const int lane = threadIdx.x & 31;
    const int t = blockIdx.x * 8 + warp;
    if (t >= NTOK) return;
    const float* xr = x + (size_t)t * DIM;

    float s[NE];
#pragma unroll
    for (int e = 0; e < NE; e++) s[e] = 0.0f;
    for (int d = lane; d < DIM; d += 32) {
        float xv = xr[d];
        const float* gr = gW + d * NE;
#pragma unroll
        for (int e = 0; e < NE; e++) s[e] = fmaf(xv, gr[e], s[e]);
    }
#pragma unroll
    for (int e = 0; e < NE; e++) {
#pragma unroll
        for (int off = 16; off > 0; off >>= 1)
            s[e] += __shfl_xor_sync(0xffffffffu, s[e], off);
    }
    if (lane == 0) {
        float p[NE];
        float m = -1e30f;
#pragma unroll
        for (int e = 0; e < NE; e++) {
            float sc = fmaxf(s[e] + gb[e], EPSV);
            p[e] = sc; m = fmaxf(m, sc);
        }
        float sum = 0.0f;
#pragma unroll
        for (int e = 0; e < NE; e++) { p[e] = expf(p[e] - m); sum += p[e]; }
        float inv = 1.0f / sum;
#pragma unroll
        for (int e = 0; e < NE; e++) p[e] *= inv;

        int i0 = 0; float b0 = p[0];
#pragma unroll
        for (int e = 1; e < NE; e++) if (p[e] > b0) { b0 = p[e]; i0 = e; }
        int i1 = (i0 == 0) ? 1 : 0; float b1 = -1.0f;
#pragma unroll
        for (int e = 0; e < NE; e++) if (e != i0 && p[e] > b1) { b1 = p[e]; i1 = e; }

        float w0 = fmaxf(b0, WTHR);
        float w1 = fmaxf(b1, WTHR);
        float invtot = 1.0f / (w0 + w1);
        float c0 = w0 * invtot * 0.5f;    // fold /K
        float c1 = w1 * invtot * 0.5f;

        int p0 = atomicAdd(&g_cnt[i0], 1);
        g_tok[i0][p0] = (t << 1) | 0; g_wt[i0][p0] = c0;
        int p1 = atomicAdd(&g_cnt[i1], 1);
        g_tok[i1][p1] = (t << 1) | 1; g_wt[i1][p1] = c1;
    }
}

// x quantization: one warp per token; per-row scale, int16 split into int8 planes
__global__ __launch_bounds__(256) void xquant_kernel(const float* __restrict__ x) {
    const int warp = threadIdx.x >> 5;
    const int lane = threadIdx.x & 31;
    const int t = blockIdx.x * 8 + warp;
    const float* xr = x + (size_t)t * DIM;

    float4 v[8];
    float m = 0.0f;
#pragma unroll
    for (int i = 0; i < 8; i++) {
        v[i] = *(const float4*)(xr + i * 128 + lane * 4);
        m = fmaxf(m, fmaxf(fmaxf(fabsf(v[i].x), fabsf(v[i].y)),
                           fmaxf(fabsf(v[i].z), fabsf(v[i].w))));
    }
#pragma unroll
    for (int off = 16; off > 0; off >>= 1)
        m = fmaxf(m, __shfl_xor_sync(0xffffffffu, m, off));

    float inv = QMAX / fmaxf(m, 1e-20f);
    if (lane == 0) g_sx[t] = m / QMAX;

#pragma unroll
    for (int i = 0; i < 8; i++) {
        int X0 = __float2int_rn(v[i].x * inv);
        int X1 = __float2int_rn(v[i].y * inv);
        int X2 = __float2int_rn(v[i].z * inv);
        int X3 = __float2int_rn(v[i].w * inv);
        int h0, l0, h1, l1, h2, l2, h3, l3;
        split_fx(X0, h0, l0); split_fx(X1, h1, l1);
        split_fx(X2, h2, l2); split_fx(X3, h3, l3);
        size_t o = (size_t)t * DIM + i * 128 + lane * 4;
        *(char4*)(g_xq1 + o) = make_char4((char)h0, (char)h1, (char)h2, (char)h3);
        *(char4*)(g_xq0 + o) = make_char4((char)l0, (char)l1, (char)l2, (char)l3);
    }
}

// per-(e,f)-column max of |W| (partial d segments, atomicMax on positive-float-as-int)
__global__ __launch_bounds__(1024) void wcolmax_kernel(const float* __restrict__ W) {
    const int e = blockIdx.x;
    const int d0 = blockIdx.y * 32;
    const int f = threadIdx.x;
    float m = 0.0f;
    for (int dd = 0; dd < 32; dd++)
        m = fmaxf(m, fabsf(W[((size_t)e * DIM + d0 + dd) * DIM + f]));
    atomicMax(&g_swmax_i[e * DIM + f], __float_as_int(m));
}

// W transpose + quantize: W[e][d][f] -> planes [e][f][d] int8 hi/lo
__global__ __launch_bounds__(256) void wquant_kernel(const float* __restrict__ W) {
    __shared__ float tile[32][33];
    const int e  = blockIdx.z;
    const int d0 = blockIdx.y * 32;
    const int f0 = blockIdx.x * 32;
    const int t  = threadIdx.x;
    const int r  = t >> 5;     // 0..7
    const int c  = t & 31;
#pragma unroll
    for (int i = 0; i < 4; i++)
        tile[r + 8 * i][c] = W[((size_t)e * DIM + d0 + r + 8 * i) * DIM + f0 + c];
    __syncthreads();

    const int fl = t >> 3;         // 0..31 local f
    const int d4 = (t & 7) * 4;    // 0..28 local d (4 each)
    const int f  = f0 + fl;
    float mx = __int_as_float(g_swmax_i[e * DIM + f]);
    float inv = QMAX / fmaxf(mx, 1e-20f);

    int h[4], l[4];
#pragma unroll
    for (int j = 0; j < 4; j++) {
        int X = __float2int_rn(tile[d4 + j][fl] * inv);
        split_fx(X, h[j], l[j]);
    }
    size_t o = ((size_t)e * DIM + f) * DIM + d0 + d4;
    *(char4*)(g_wq1 + o) = make_char4((char)h[0], (char)h[1], (char)h[2], (char)h[3]);
    *(char4*)(g_wq0 + o) = make_char4((char)l[0], (char)l[1], (char)l[2], (char)l[3]);

    if (blockIdx.y == 0 && t < 32)
        g_sw[e * DIM + f0 + t] = __int_as_float(g_swmax_i[e * DIM + f0 + t]) / QMAX;
}

// -------- int8 3-pass expert GEMM (IMMA m16n8k32), cp.async double-buffer --------
__global__ __launch_bounds__(256) void moe_gemm_kernel(const float* __restrict__ eb)
{
    extern __shared__ char smem[];
    const int e   = blockIdx.z;
    const int cnt = g_cnt[e];
    const int m0  = blockIdx.y * BM;
    if (m0 >= cnt) return;
    const int f0  = blockIdx.x * BN;

    const uint32_t sb = smem_u32(smem);
    const int tid  = threadIdx.x;
    const int lane = tid & 31;
    const int wid  = tid >> 5;
    const int wm   = wid & 1;     // 2 warp rows (64 m)
    const int wn   = wid >> 1;    // 4 warp cols (32 n)

    int*   stok  = (int*)(smem + SM_TOK);
    float* swt   = (float*)(smem + SM_WT);
    float* sxs   = (float*)(smem + SM_SX);
    float* sws   = (float*)(smem + SM_SW);
    float* sbias = (float*)(smem + SM_BIAS);
    if (tid < BM) {
        int idx = m0 + tid;
        int te = (idx < cnt) ? g_tok[e][idx] : 0;
        stok[tid] = te;
        swt[tid]  = (idx < cnt) ? g_wt[e][idx] : 0.0f;
        sxs[tid]  = g_sx[te >> 1];
        sws[tid]  = g_sw[e * DIM + f0 + tid];
        sbias[tid] = eb[(size_t)e * DIM + f0 + tid];
    }
    __syncthreads();

    // copy mappings: per plane 512 x 16B ops -> 2 per thread (j=0,1)
    const int ar0 = tid >> 2, ar1 = (tid + 256) >> 2;   // rows 0..127
    const int ac16 = tid & 3;
    const int atok0 = stok[ar0] >> 1, atok1 = stok[ar1] >> 1;
    const uint32_t ad0 = (uint32_t)(ar0 * ASTRIDE + ac16 * 16);
    const uint32_t ad1 = (uint32_t)(ar1 * ASTRIDE + ac16 * 16);
    const signed char* Wq1 = g_wq1 + ((size_t)e * DIM + f0) * DIM;
    const signed char* Wq0 = g_wq0 + ((size_t)e * DIM + f0) * DIM;

    // prologue: chunk 0 -> stage 0
    {
        const uint32_t s0 = sb + SM_TILES;
        CPA16(s0 + OFF_A1 + ad0, g_xq1 + (size_t)atok0 * DIM + ac16 * 16);
        CPA16(s0 + OFF_A1 + ad1, g_xq1 + (size_t)atok1 * DIM + ac16 * 16);
        CPA16(s0 + OFF_A0 + ad0, g_xq0 + (size_t)atok0 * DIM + ac16 * 16);
        CPA16(s0 + OFF_A0 + ad1, g_xq0 + (size_t)atok1 * DIM + ac16 * 16);
        CPA16(s0 + OFF_B1 + ad0, Wq1 + (size_t)ar0 * DIM + ac16 * 16);
        CPA16(s0 + OFF_B1 + ad1, Wq1 + (size_t)ar1 * DIM + ac16 * 16);
        CPA16(s0 + OFF_B0 + ad0, Wq0 + (size_t)ar0 * DIM + ac16 * 16);
        CPA16(s0 + OFF_B0 + ad1, Wq0 + (size_t)ar1 * DIM + ac16 * 16);
        CPA_COMMIT();
    }

    int ach[4][4][4], acl[4][4][4];   // hi(x65536) and lo(x256) s32 accumulators
#pragma unroll
    for (int i = 0; i < 4; i++)
#pragma unroll
        for (int j = 0; j < 4; j++)
#pragma unroll
            for (int r = 0; r < 4; r++) { ach[i][j][r] = 0; acl[i][j][r] = 0; }

    // ldmatrix lane offsets
    const uint32_t a_off = (uint32_t)((wm * 64 + (lane & 15)) * ASTRIDE + ((lane >> 4) & 1) * 16);
    const uint32_t b_off = (uint32_t)((wn * 32 + ((lane >> 4) & 1) * 8 + (lane & 7)) * ASTRIDE
                                      + ((lane >> 3) & 1) * 16);

    for (int c = 0; c < NKCH; c++) {
        CPA_WAIT0();
        __syncthreads();

        if (c + 1 < NKCH) {
            const uint32_t sn = sb + SM_TILES + ((c + 1) & 1) * STAGE_SZ;
            const int k0 = (c + 1) * BK;
            CPA16(sn + OFF_A1 + ad0, g_xq1 + (size_t)atok0 * DIM + k0 + ac16 * 16);
            CPA16(sn + OFF_A1 + ad1, g_xq1 + (size_t)atok1 * DIM + k0 + ac16 * 16);
            CPA16(sn + OFF_A0 + ad0, g_xq0 + (size_t)atok0 * DIM + k0 + ac16 * 16);
            CPA16(sn + OFF_A0 + ad1, g_xq0 + (size_t)atok1 * DIM + k0 + ac16 * 16);
            CPA16(sn + OFF_B1 + ad0, Wq1 + (size_t)ar0 * DIM + k0 + ac16 * 16);
            CPA16(sn + OFF_B1 + ad1, Wq1 + (size_t)ar1 * DIM + k0 + ac16 * 16);
            CPA16(sn + OFF_B0 + ad0, Wq0 + (size_t)ar0 * DIM + k0 + ac16 * 16);
            CPA16(sn + OFF_B0 + ad1, Wq0 + (size_t)ar1 * DIM + k0 + ac16 * 16);
            CPA_COMMIT();
        }

        const uint32_t sc = sb + SM_TILES + (c & 1) * STAGE_SZ;
#pragma unroll
        for (int ks = 0; ks < 2; ks++) {       // 2 x k32 per 64B chunk
            uint32_t a1f[4][4], a0f[4][4];
#pragma unroll
            for (int mt = 0; mt < 4; mt++) {
                uint32_t ad = sc + a_off + (uint32_t)(mt * 16 * ASTRIDE + ks * 32);
                ldsm_x4(a1f[mt], ad + OFF_A1);
                ldsm_x4(a0f[mt], ad + OFF_A0);
            }
#pragma unroll
            for (int np = 0; np < 2; np++) {   // 2 pairs of n8 tiles
                uint32_t b1f[4], b0f[4];
                uint32_t bd = sc + b_off + (uint32_t)(np * 16 * ASTRIDE + ks * 32);
                ldsm_x4(b1f, bd + OFF_B1);
                ldsm_x4(b0f, bd + OFF_B0);
#pragma unroll
                for (int mt = 0; mt < 4; mt++) {
                    mma_s8(ach[mt][np * 2 + 0], a1f[mt], b1f[0], b1f[1]);
                    mma_s8(ach[mt][np * 2 + 1], a1f[mt], b1f[2], b1f[3]);
                    mma_s8(acl[mt][np * 2 + 0], a1f[mt], b0f[0], b0f[1]);
                    mma_s8(acl[mt][np * 2 + 1], a1f[mt], b0f[2], b0f[3]);
                    mma_s8(acl[mt][np * 2 + 0], a0f[mt], b1f[0], b1f[1]);
                    mma_s8(acl[mt][np * 2 + 1], a0f[mt], b1f[2], b1f[3]);
                }
            }
        }
        __syncthreads();
    }

    // ---- epilogue: dequant + weight + bias, write-once into g_part ----
#pragma unroll
    for (int mt = 0; mt < 4; mt++) {
#pragma unroll
        for (int half = 0; half < 2; half++) {
            int m = wm * 64 + mt * 16 + (lane >> 2) + half * 8;
            if (m0 + m < cnt) {
                int te = stok[m];
                float w = swt[m];
                float sx = sxs[m];
                float* dst = g_part + ((size_t)(te & 1) * NTOK + (size_t)(te >> 1)) * DIM
                           + f0 + wn * 32;
#pragma unroll
                for (int nidx = 0; nidx < 4; nidx++) {
                    int cb = nidx * 8 + (lane & 3) * 2;
                    float sc0 = sx * sws[wn * 32 + cb];
                    float sc1 = sx * sws[wn * 32 + cb + 1];
                    float d0 = (float)ach[mt][nidx][half * 2 + 0] * 65536.f
                             + (float)acl[mt][nidx][half * 2 + 0] * 256.f;
                    float d1 = (float)ach[mt][nidx][half * 2 + 1] * 65536.f
                             + (float)acl[mt][nidx][half * 2 + 1] * 256.f;
                    float v0 = w * (d0 * sc0 + sbias[wn * 32 + cb]);
                    float v1 = w * (d1 * sc1 + sbias[wn * 32 + cb + 1]);
                    *(float2*)(dst + cb) = make_float2(v0, v1);
                }
            }
        }
    }
}

// out = part0 + part1
__global__ __launch_bounds__(256) void combine_kernel(float* __restrict__ out) {
    size_t i = ((size_t)blockIdx.x * 256 + threadIdx.x) * 4;
    const float4 a = *(const float4*)(g_part + i);
    const float4 b = *(const float4*)(g_part + (size_t)NTOK * DIM + i);
    *(float4*)(out + i) = make_float4(a.x + b.x, a.y + b.y, a.z + b.z, a.w + b.w);
}

// ================= host =================
extern "C" void kernel_launch(void* const* d_in, const int* in_sizes, int n_in,
                              void* d_out, int out_size)
{
    const float* x  = (const float*)d_in[0];   // [4,2048,1024]
    const float* gW = (const float*)d_in[1];   // [1024,8]
    const float* gb = (const float*)d_in[2];   // [8]
    const float* eW = (const float*)d_in[3];   // [8,1024,1024]
    const float* eb = (const float*)d_in[4];   // [8,1024]
    float* out = (float*)d_out;
    (void)in_sizes; (void)n_in; (void)out_size;

    init_kernel<<<NE, 1024>>>();
    gating_kernel<<<NTOK / 8, 256>>>(x, gW, gb);
    xquant_kernel<<<NTOK / 8, 256>>>(x);
    wcolmax_kernel<<<dim3(NE, DIM / 32), 1024>>>(eW);
    wquant_kernel<<<dim3(DIM / 32, DIM / 32, NE), 256>>>(eW);

    cudaFuncSetAttribute(moe_gemm_kernel,
                         cudaFuncAttributeMaxDynamicSharedMemorySize, SM_TOTAL);
    dim3 grid(DIM / BN, NTOK / BM, NE);   // (8, 64, 8)
    moe_gemm_kernel<<<grid, 256, SM_TOTAL>>>(eb);

    combine_kernel<<<(NTOK * DIM / 4) / 256, 256>>>(out);
}

// round 7
// speedup vs baseline: 4.1898x; 4.1898x over previous
#include <cuda_runtime.h>
#include <cuda_fp16.h>
#include <cstdint>
#include <math.h>

// Problem constants
#define NTOK 8192      // B*S
#define DIM  1024
#define NE   8
#define EPSV 1e-4f
#define WTHR 0.1f

// GEMM tile
#define BM 128
#define BN 128
#define BK 64
#define NKCH (DIM / BK)   // 16

// smem (dynamic, bytes)
#define ASTRIDE 144                   // 64 fp16 (128B) + 16B pad
#define BSTRIDE 272                   // 128 fp16 (256B) + 16B pad
#define ABUF    (128 * ASTRIDE)       // 18432
#define BBUF    (64 * BSTRIDE)        // 17408
#define OFF_A   0
#define OFF_B   ABUF
#define STAGE_SZ (ABUF + BBUF)        // 35840
#define SM_TOK   0
#define SM_WT    512
#define SM_BIAS  1024
#define SM_TILES 1536
#define SM_TOTAL (SM_TILES + 2 * STAGE_SZ)   // 73216

// -------- device scratch --------
__device__ int   g_cnt[NE];
__device__ int   g_tok[NE][NTOK];     // (token<<1) | slot
__device__ float g_wt [NE][NTOK];
__device__ __half g_xh[(size_t)NTOK * DIM];
__device__ __half g_wh[(size_t)NE * DIM * DIM];   // natural [e][d][f]
__device__ float g_part[2ull * NTOK * DIM];

// -------- helpers --------
__device__ __forceinline__ uint32_t smem_u32(const void* p) {
    uint32_t a;
    asm("{ .reg .u64 t; cvta.to.shared.u64 t, %1; cvt.u32.u64 %0, t; }" : "=r"(a) : "l"(p));
    return a;
}
__device__ __forceinline__ void ldsm_x4(uint32_t* r, uint32_t addr) {
    asm volatile("ldmatrix.sync.aligned.m8n8.x4.shared.b16 {%0,%1,%2,%3}, [%4];"
                 : "=r"(r[0]), "=r"(r[1]), "=r"(r[2]), "=r"(r[3]) : "r"(addr));
}
__device__ __forceinline__ void ldsm_x4_t(uint32_t* r, uint32_t addr) {
    asm volatile("ldmatrix.sync.aligned.m8n8.x4.trans.shared.b16 {%0,%1,%2,%3}, [%4];"
                 : "=r"(r[0]), "=r"(r[1]), "=r"(r[2]), "=r"(r[3]) : "r"(addr));
}
__device__ __forceinline__ void mma_f16(float* d, const uint32_t* a, uint32_t b0, uint32_t b1) {
    asm volatile(
        "mma.sync.aligned.m16n8k16.row.col.f32.f16.f16.f32 "
        "{%0,%1,%2,%3}, {%4,%5,%6,%7}, {%8,%9}, {%0,%1,%2,%3};"
        : "+f"(d[0]), "+f"(d[1]), "+f"(d[2]), "+f"(d[3])
        : "r"(a[0]), "r"(a[1]), "r"(a[2]), "r"(a[3]), "r"(b0), "r"(b1));
}
#define CPA16(dst, src) \
    asm volatile("cp.async.cg.shared.global [%0], [%1], 16;" :: "r"(dst), "l"(src) : "memory")
#define CPA_COMMIT() asm volatile("cp.async.commit_group;" ::: "memory")
#define CPA_WAIT0()  asm volatile("cp.async.wait_group 0;" ::: "memory")

// ================= kernels =================

__global__ void init_counts_kernel() {
    if (threadIdx.x < NE) g_cnt[threadIdx.x] = 0;
}

// gating: one warp per token
__global__ __launch_bounds__(256) void gating_kernel(
    const float* __restrict__ x, const float* __restrict__ gW, const float* __restrict__ gb)
{
    const int warp = threadIdx.x >> 5;
    const int lane = threadIdx.x & 31;
    const int t = blockIdx.x * 8 + warp;
    if (t >= NTOK) return;
    const float* xr = x + (size_t)t * DIM;

    float s[NE];
#pragma unroll
    for (int e = 0; e < NE; e++) s[e] = 0.0f;
    for (int d = lane; d < DIM; d += 32) {
        float xv = xr[d];
        const float* gr = gW + d * NE;
#pragma unroll
        for (int e = 0; e < NE; e++) s[e] = fmaf(xv, gr[e], s[e]);
    }
#pragma unroll
    for (int e = 0; e < NE; e++) {
#pragma unroll
        for (int off = 16; off > 0; off >>= 1)
            s[e] += __shfl_xor_sync(0xffffffffu, s[e], off);
    }
    if (lane == 0) {
        float p[NE];
        float m = -1e30f;
#pragma unroll
        for (int e = 0; e < NE; e++) {
            float sc = fmaxf(s[e] + gb[e], EPSV);
            p[e] = sc; m = fmaxf(m, sc);
        }
        float sum = 0.0f;
#pragma unroll
        for (int e = 0; e < NE; e++) { p[e] = expf(p[e] - m); sum += p[e]; }
        float inv = 1.0f / sum;
#pragma unroll
        for (int e = 0; e < NE; e++) p[e] *= inv;

        int i0 = 0; float b0 = p[0];
#pragma unroll
        for (int e = 1; e < NE; e++) if (p[e] > b0) { b0 = p[e]; i0 = e; }
        int i1 = (i0 == 0) ? 1 : 0; float b1 = -1.0f;
#pragma unroll
        for (int e = 0; e < NE; e++) if (e != i0 && p[e] > b1) { b1 = p[e]; i1 = e; }

        float w0 = fmaxf(b0, WTHR);
        float w1 = fmaxf(b1, WTHR);
        float invtot = 1.0f / (w0 + w1);
        float c0 = w0 * invtot * 0.5f;    // fold /K
        float c1 = w1 * invtot * 0.5f;

        int p0 = atomicAdd(&g_cnt[i0], 1);
        g_tok[i0][p0] = (t << 1) | 0; g_wt[i0][p0] = c0;
        int p1 = atomicAdd(&g_cnt[i1], 1);
        g_tok[i1][p1] = (t << 1) | 1; g_wt[i1][p1] = c1;
    }
}

// fp32 -> fp16 converters (pure streaming, float4 -> 2x half2)
__global__ __launch_bounds__(256) void xcvt_kernel(const float* __restrict__ x) {
    size_t i = ((size_t)blockIdx.x * 256 + threadIdx.x) * 4;
    float4 v = *(const float4*)(x + i);
    __half2 h0 = __float22half2_rn(make_float2(v.x, v.y));
    __half2 h1 = __float22half2_rn(make_float2(v.z, v.w));
    *(uint2*)(g_xh + i) = make_uint2(*(uint32_t*)&h0, *(uint32_t*)&h1);
}
__global__ __launch_bounds__(256) void wcvt_kernel(const float* __restrict__ W) {
    size_t i = ((size_t)blockIdx.x * 256 + threadIdx.x) * 4;
    float4 v = *(const float4*)(W + i);
    __half2 h0 = __float22half2_rn(make_float2(v.x, v.y));
    __half2 h1 = __float22half2_rn(make_float2(v.z, v.w));
    *(uint2*)(g_wh + i) = make_uint2(*(uint32_t*)&h0, *(uint32_t*)&h1);
}

// -------- fp16 single-pass expert GEMM, cp.async double-buffer --------
__global__ __launch_bounds__(256) void moe_gemm_kernel(const float* __restrict__ eb)
{
    extern __shared__ char smem[];
    const int e   = blockIdx.z;
    const int cnt = g_cnt[e];
    const int m0  = blockIdx.y * BM;
    if (m0 >= cnt) return;
    const int f0  = blockIdx.x * BN;

    const uint32_t sb = smem_u32(smem);
    const int tid  = threadIdx.x;
    const int lane = tid & 31;
    const int wid  = tid >> 5;
    const int wm   = wid & 1;     // 2 warp rows (64 m)
    const int wn   = wid >> 1;    // 4 warp cols (32 n)

    int*   stok  = (int*)(smem + SM_TOK);
    float* swt   = (float*)(smem + SM_WT);
    float* sbias = (float*)(smem + SM_BIAS);
    if (tid < BM) {
        int idx = m0 + tid;
        stok[tid] = (idx < cnt) ? g_tok[e][idx] : 0;
        swt[tid]  = (idx < cnt) ? g_wt[e][idx]  : 0.0f;
        sbias[tid] = eb[(size_t)e * DIM + f0 + tid];
    }
    __syncthreads();

    // copy mappings
    // A: 128 rows x 128B (8 x 16B): 1024 ops / 256 thr = 4 each
    int      atokr[4];
    uint32_t adst[4];
    const int acol = tid & 7;
#pragma unroll
    for (int j = 0; j < 4; j++) {
        int idx = tid + j * 256;
        int row = idx >> 3;
        atokr[j] = stok[row] >> 1;
        adst[j]  = (uint32_t)(row * ASTRIDE + acol * 16);
    }
    // B: 64 k-rows x 256B (16 x 16B): 1024 ops / 256 thr = 4 each
    const int bcol = tid & 15;
    int      brow[4];
    uint32_t bdst[4];
#pragma unroll
    for (int j = 0; j < 4; j++) {
        int idx = tid + j * 256;
        brow[j] = idx >> 4;
        bdst[j] = (uint32_t)(brow[j] * BSTRIDE + bcol * 16);
    }
    const __half* Wh = g_wh + (size_t)e * DIM * DIM + f0 + bcol * 8;

    // prologue: chunk 0 -> stage 0
    {
        const uint32_t s0 = sb + SM_TILES;
#pragma unroll
        for (int j = 0; j < 4; j++)
            CPA16(s0 + OFF_A + adst[j], g_xh + (size_t)atokr[j] * DIM + acol * 8);
#pragma unroll
        for (int j = 0; j < 4; j++)
            CPA16(s0 + OFF_B + bdst[j], Wh + (size_t)brow[j] * DIM);
        CPA_COMMIT();
    }

    float acc[4][4][4];
#pragma unroll
    for (int i = 0; i < 4; i++)
#pragma unroll
        for (int jj = 0; jj < 4; jj++)
#pragma unroll
            for (int r = 0; r < 4; r++) acc[i][jj][r] = 0.0f;

    const uint32_t a_off = (uint32_t)((wm * 64 + (lane & 15)) * ASTRIDE + ((lane >> 4) & 1) * 16);
    const uint32_t b_off = (uint32_t)((lane & 15) * BSTRIDE + wn * 64 + ((lane >> 4) & 1) * 16);

    for (int c = 0; c < NKCH; c++) {
        CPA_WAIT0();
        __syncthreads();

        if (c + 1 < NKCH) {
            const uint32_t sn = sb + SM_TILES + ((c + 1) & 1) * STAGE_SZ;
            const int k0 = (c + 1) * BK;
#pragma unroll
            for (int j = 0; j < 4; j++)
                CPA16(sn + OFF_A + adst[j], g_xh + (size_t)atokr[j] * DIM + k0 + acol * 8);
#pragma unroll
            for (int j = 0; j < 4; j++)
                CPA16(sn + OFF_B + bdst[j], Wh + (size_t)(k0 + brow[j]) * DIM);
            CPA_COMMIT();
        }

        const uint32_t sc = sb + SM_TILES + (c & 1) * STAGE_SZ;
#pragma unroll
        for (int ks = 0; ks < 4; ks++) {
            uint32_t ah[4][4];
#pragma unroll
            for (int mt = 0; mt < 4; mt++) {
                uint32_t ad = sc + OFF_A + a_off + (uint32_t)(mt * 16 * ASTRIDE + ks * 32);
                ldsm_x4(ah[mt], ad);
            }
#pragma unroll
            for (int nb2 = 0; nb2 < 2; nb2++) {
                uint32_t bh[4];
                uint32_t bd = sc + OFF_B + b_off + (uint32_t)(ks * 16 * BSTRIDE + nb2 * 32);
                ldsm_x4_t(bh, bd);
#pragma unroll
                for (int mt = 0; mt < 4; mt++) {
                    mma_f16(acc[mt][nb2 * 2 + 0], ah[mt], bh[0], bh[1]);
                    mma_f16(acc[mt][nb2 * 2 + 1], ah[mt], bh[2], bh[3]);
                }
            }
        }
        __syncthreads();
    }

    // ---- epilogue: write-once into g_part[slot][tok][f] ----
#pragma unroll
    for (int mt = 0; mt < 4; mt++) {
#pragma unroll
        for (int half = 0; half < 2; half++) {
            int m = wm * 64 + mt * 16 + (lane >> 2) + half * 8;
            if (m0 + m < cnt) {
                int te = stok[m];
                float w = swt[m];
                float* dst = g_part + ((size_t)(te & 1) * NTOK + (size_t)(te >> 1)) * DIM
                           + f0 + wn * 32;
#pragma unroll
                for (int nidx = 0; nidx < 4; nidx++) {
                    int cb = nidx * 8 + (lane & 3) * 2;
                    float v0 = w * (acc[mt][nidx][half * 2 + 0] + sbias[wn * 32 + cb]);
                    float v1 = w * (acc[mt][nidx][half * 2 + 1] + sbias[wn * 32 + cb + 1]);
                    *(float2*)(dst + cb) = make_float2(v0, v1);
                }
            }
        }
    }
}

// out = part0 + part1
__global__ __launch_bounds__(256) void combine_kernel(float* __restrict__ out) {
    size_t i = ((size_t)blockIdx.x * 256 + threadIdx.x) * 4;
    const float4 a = *(const float4*)(g_part + i);
    const float4 b = *(const float4*)(g_part + (size_t)NTOK * DIM + i);
    *(float4*)(out + i) = make_float4(a.x + b.x, a.y + b.y, a.z + b.z, a.w + b.w);
}

// ================= host =================
extern "C" void kernel_launch(void* const* d_in, const int* in_sizes, int n_in,
                              void* d_out, int out_size)
{
    const float* x  = (const float*)d_in[0];   // [4,2048,1024]
    const float* gW = (const float*)d_in[1];   // [1024,8]
    const float* gb = (const float*)d_in[2];   // [8]
    const float* eW = (const float*)d_in[3];   // [8,1024,1024]
    const float* eb = (const float*)d_in[4];   // [8,1024]
    float* out = (float*)d_out;
    (void)in_sizes; (void)n_in; (void)out_size;

    init_counts_kernel<<<1, 32>>>();
    gating_kernel<<<NTOK / 8, 256>>>(x, gW, gb);
    xcvt_kernel<<<(NTOK * DIM / 4) / 256, 256>>>(x);
    wcvt_kernel<<<(NE * DIM * DIM / 4) / 256, 256>>>(eW);

    cudaFuncSetAttribute(moe_gemm_kernel,
                         cudaFuncAttributeMaxDynamicSharedMemorySize, SM_TOTAL);
    dim3 grid(DIM / BN, NTOK / BM, NE);   // (8, 64, 8)
    moe_gemm_kernel<<<grid, 256, SM_TOTAL>>>(eb);

    combine_kernel<<<(NTOK * DIM / 4) / 256, 256>>>(out);
}